// round 8
// baseline (speedup 1.0000x reference)
#include <cuda_runtime.h>
#include <cstdint>

// NVAR feature expansion.  X: (8,4,4096) f32 -> out: (8,4,3996,231) f32
//   out[p, 0]      = 1
//   out[p, 1+k]    = lin[k] = X[br, t + 82 + 2k]
//   out[p, 11+m]   = lin[a]*lin[b]*lin[c], lex triples a<=b<=c over 0..9
//
// R5: compute tile in smem (compile-time monomial unroll, conflict-free STS,
// stride 231 mod 32 = 7), then ship the whole contiguous 29568-byte tile to
// global with ONE cp.async.bulk (TMA bulk store). This removes the LDS+STG
// round trip that made R4 L1-wavefront-bound (354 MB -> 118 MB of L1 traffic).

constexpr int K_TAPS   = 10;
constexpr int NF       = 231;
constexpr int N_TIME   = 4096;
constexpr int T_OUT    = 3996;
constexpr int BASE_OFF = 82;           // TRANSIENTS - (K-1)*SKIP
constexpr int SKIP     = 2;

constexpr int NP_BLK   = 32;                        // points per CTA
constexpr int NTHREADS = 128;
constexpr int NSEG     = 4;
constexpr int FL_BLK   = NP_BLK * NF;               // 7392 floats
constexpr int GRID     = (8 * 4 * T_OUT) / NP_BLK;  // 3996 exactly
constexpr int SMEM_B   = FL_BLK * 4;                // 29568 bytes (16B multiple)

__device__ constexpr int SEG_LO[NSEG + 1] = {0, 58, 116, 174, 231};

__global__ __launch_bounds__(NTHREADS) void nvar_kernel(const float* __restrict__ X,
                                                        float* __restrict__ out) {
    extern __shared__ __align__(128) float s_feat[];   // point-major, stride NF

    const int tid = threadIdx.x;
    const int q   = tid >> 5;                       // warp = feature segment
    const int lp  = tid & 31;                       // lane = local point
    const int p   = blockIdx.x * NP_BLK + lp;
    const int br  = p / T_OUT;
    const int t   = p - br * T_OUT;

    // ---- Phase 1: taps in registers, compile-time segment emission ----
    float lin[K_TAPS];
    const float* xb = X + br * N_TIME + t + BASE_OFF;
    #pragma unroll
    for (int k = 0; k < K_TAPS; ++k) lin[k] = xb[SKIP * k];

    float* o = s_feat + lp * NF;

    #pragma unroll
    for (int Q = 0; Q < NSEG; ++Q) {
        if (q == Q) {
            const int lo = SEG_LO[Q];
            const int hi = SEG_LO[Q + 1];
            if (Q == 0) {
                o[0] = 1.0f;
                #pragma unroll
                for (int k = 0; k < K_TAPS; ++k) o[1 + k] = lin[k];
            }
            int m = 11;                             // compile-time after unroll
            #pragma unroll
            for (int a = 0; a < K_TAPS; ++a) {
                #pragma unroll
                for (int b = a; b < K_TAPS; ++b) {
                    const float pab = lin[a] * lin[b];
                    #pragma unroll
                    for (int c = b; c < K_TAPS; ++c) {
                        if (m >= lo && m < hi) o[m] = pab * lin[c];
                        ++m;
                    }
                }
            }
        }
    }
    __syncthreads();

    // ---- Phase 2: single TMA bulk store smem -> global ----
    if (tid == 0) {
        asm volatile("fence.proxy.async.shared::cta;" ::: "memory");
        uint32_t saddr = (uint32_t)__cvta_generic_to_shared(s_feat);
        char*    gptr  = reinterpret_cast<char*>(out) + (size_t)blockIdx.x * SMEM_B;
        asm volatile(
            "cp.async.bulk.global.shared::cta.bulk_group [%0], [%1], %2;"
            :: "l"(gptr), "r"(saddr), "n"(SMEM_B) : "memory");
        asm volatile("cp.async.bulk.commit_group;" ::: "memory");
        asm volatile("cp.async.bulk.wait_group 0;" ::: "memory");
    }
}

extern "C" void kernel_launch(void* const* d_in, const int* in_sizes, int n_in,
                              void* d_out, int out_size) {
    const float* X   = (const float*)d_in[0];
    float*       out = (float*)d_out;
    (void)in_sizes; (void)n_in; (void)out_size;
    nvar_kernel<<<GRID, NTHREADS, SMEM_B>>>(X, out);
}